// round 16
// baseline (speedup 1.0000x reference)
#include <cuda_runtime.h>
#include <cuda_bf16.h>
#include <cooperative_groups.h>

namespace cg = cooperative_groups;

#define D    256
#define F    1024
#define NL   4
#define NC   10
#define CS   8
#define TPB  256
#define M    4      // batch elements per cluster

__device__ __forceinline__ float gelu_tanh(float x) {
    const float c = 0.7978845608028654f;
    float u = c * (x + 0.044715f * x * x * x);
    return 0.5f * x * (1.0f + tanhf(u));
}

// fmaf of one component of a float4 y-vector, compile-time selected
#define FMA_C(acc, w, yv, i2)                                            \
    {   float yk_ = (i2) == 0 ? (yv).x : (i2) == 1 ? (yv).y              \
                  : (i2) == 2 ? (yv).z : (yv).w;                         \
        (acc).x = fmaf(yk_, (w).x, (acc).x);                             \
        (acc).y = fmaf(yk_, (w).y, (acc).y);                             \
        (acc).z = fmaf(yk_, (w).z, (acc).z);                             \
        (acc).w = fmaf(yk_, (w).w, (acc).w); }

__global__ void __launch_bounds__(TPB, 1) __cluster_dims__(CS, 1, 1)
performer_cls_kernel(const int*   __restrict__ xx,
                     const float* __restrict__ emb_tok,
                     const float* __restrict__ emb_pos,
                     const float* __restrict__ ln1_s,
                     const float* __restrict__ ln1_b,
                     const float* __restrict__ wv,
                     const float* __restrict__ wo,
                     const float* __restrict__ bo,
                     const float* __restrict__ ln2_s,
                     const float* __restrict__ ln2_b,
                     const float* __restrict__ w1,
                     const float* __restrict__ b1v,
                     const float* __restrict__ w2,
                     const float* __restrict__ b2v,
                     const float* __restrict__ wcls,
                     const float* __restrict__ bcls,
                     float* __restrict__ out,
                     int N)
{
    __shared__ __align__(16) float sh_h[M * D];     // residual (replicated)
    __shared__ __align__(16) float sh_y[M * D];     // LN output
    __shared__ __align__(16) float sh_c[M * 128];   // chunk staging
    __shared__ float  sh_ar[CS * M * 32];           // reduce-scatter slots
    __shared__ float  sh_sq[CS * M * 2];            // LN partial-sum slots
    __shared__ float4 ps4[1056];                    // split-K partials
    __shared__ float  red[8];                       // (s,q) totals

    float* psf = (float*)ps4;

    cg::cluster_group cluster = cg::this_cluster();
    const int tid = threadIdx.x;
    const int r   = (int)cluster.block_rank();
    const int b0  = (blockIdx.x >> 3) * M;

    const int c4  = tid & 7;            // matvec1-A: float4-col in 8-group
    const int ks  = tid >> 3;           // matvec1-A: K-slice 0..31
    const int c4b = tid & 31;           // matvec1-B: float4-col in 32-group
    const int ksb = tid >> 5;           // matvec1-B: K-slice 0..7
    const int cc  = tid & 63;           // matvec2: float4-col over 256 cols
    const int ss  = tid >> 6;           // matvec2: K-slice 0..3
    const int j0  = r * 32;
    const int j0b = r * 128;
    const int rk   = tid >> 5;
    const int lane = tid & 31;

    const float4* Y4 = (const float4*)sh_y;
    const float4* C4 = (const float4*)sh_c;

    // ---- heavy-stage LN: sum slots + normalize (1 bar.sync each) ----
    auto ln_normalize = [&](const float* sc, const float* bi) {
        if (tid < 8) {
            float acc = 0.0f;
            #pragma unroll
            for (int r2 = 0; r2 < CS; ++r2) acc += sh_sq[r2 * 8 + tid];
            red[tid] = acc;
        }
        __syncthreads();
        float scv = sc[tid], biv = bi[tid];
        #pragma unroll
        for (int m = 0; m < M; ++m) {
            float mu  = red[m * 2] * (1.0f / D);
            float var = red[m * 2 + 1] * (1.0f / D) - mu * mu;
            float inv = rsqrtf(var + 1e-5f);
            sh_y[m * D + tid] = (sh_h[m * D + tid] - mu) * inv * scv + biv;
        }
        __syncthreads();
    };

    // ---- 4-slice reduce of full-width partials + reduce-scatter ----
    auto reduce_scatter = [&]() {
        float po[M];
        #pragma unroll
        for (int m = 0; m < M; ++m) {
            float acc = psf[m * 1056 + tid];
            #pragma unroll
            for (int s = 1; s < 4; ++s) acc += psf[m * 1056 + s * 264 + tid];
            po[m] = acc;
        }
        float* dst = cluster.map_shared_rank(sh_ar, rk);
        #pragma unroll
        for (int m = 0; m < M; ++m)
            dst[r * 128 + m * 32 + lane] = po[m];
    };

    // ---- tiny stage: assemble chunk + bias + residual, LN partials, bcast ----
    auto tiny_stage = [&](const float* bias) {
        if (tid < 128) {
            int m = tid >> 5, col = tid & 31;       // warp == m
            float acc = bias[j0 + col];
            #pragma unroll
            for (int r2 = 0; r2 < CS; ++r2) acc += sh_ar[r2 * 128 + m * 32 + col];
            float hn = sh_h[m * D + j0 + col] + acc;
            float s = hn, q = hn * hn;
            #pragma unroll
            for (int o = 16; o > 0; o >>= 1) {
                s += __shfl_xor_sync(0xffffffffu, s, o);
                q += __shfl_xor_sync(0xffffffffu, q, o);
            }
            sh_c[m * 32 + col] = hn;
            if (col < CS) {                          // lane col -> rank col
                float* dsq = cluster.map_shared_rank(sh_sq, col);
                dsq[r * 8 + m * 2]     = s;
                dsq[r * 8 + m * 2 + 1] = q;
            }
        }
        __syncthreads();
        float* dst = cluster.map_shared_rank(sh_h, rk);
        #pragma unroll
        for (int m = 0; m < M; ++m)
            dst[m * D + j0 + lane] = sh_c[m * 32 + lane];
    };

    // ---- init: h0 (replicated) + initial LN1 partials (all local) ----
    {
        #pragma unroll
        for (int m = 0; m < M; ++m) {
            const int tok = xx[(size_t)(b0 + m) * N];
            sh_h[m * D + tid] = emb_tok[(size_t)tok * D + tid] + emb_pos[tid];
        }
        __syncthreads();
        int w = tid >> 5, lane2 = tid & 31;          // warp w handles chunk w
        #pragma unroll
        for (int m = 0; m < M; ++m) {
            float v = sh_h[m * D + w * 32 + lane2];
            float s = v, q = v * v;
            #pragma unroll
            for (int o = 16; o > 0; o >>= 1) {
                s += __shfl_xor_sync(0xffffffffu, s, o);
                q += __shfl_xor_sync(0xffffffffu, q, o);
            }
            if (lane2 == 0) {
                sh_sq[w * 8 + m * 2]     = s;
                sh_sq[w * 8 + m * 2 + 1] = q;
            }
        }
        __syncthreads();
    }

    for (int l = 0; l < NL; ++l) {
        // ================== heavy stage A: attention pair ==================
        ln_normalize(ln1_s + l * D, ln1_b + l * D);
        {
            // (1) v0 chunk = y @ wv[:, j0:j0+32]
            const float4* W4 = (const float4*)(wv + (size_t)l * D * D);
            float4 a[M];
            #pragma unroll
            for (int m = 0; m < M; ++m) a[m] = make_float4(0.f, 0.f, 0.f, 0.f);
            #pragma unroll
            for (int j = 0; j < 2; ++j) {
                float4 yv[M];
                #pragma unroll
                for (int m = 0; m < M; ++m) yv[m] = Y4[m * 64 + ks * 2 + j];
                #pragma unroll
                for (int i2 = 0; i2 < 4; ++i2) {
                    int k = ks * 8 + j * 4 + i2;
                    float4 w = W4[k * 64 + r * 8 + c4];
                    #pragma unroll
                    for (int m = 0; m < M; ++m) FMA_C(a[m], w, yv[m], i2);
                }
            }
            #pragma unroll
            for (int m = 0; m < M; ++m) ps4[ks * 33 + m * 8 + c4] = a[m];
            __syncthreads();
            if (tid < 128) {
                int m = tid >> 5, col = tid & 31;
                float acc = 0.0f;
                #pragma unroll
                for (int s = 0; s < 32; ++s) acc += psf[s * 132 + m * 32 + col];
                sh_c[m * 32 + col] = acc;
            }
            __syncthreads();

            // (2) partial o (all 256 cols) from my v0 chunk rows of wo
            const float4* Wo4 = (const float4*)(wo + (size_t)l * D * D);
            float4 pa[M];
            #pragma unroll
            for (int m = 0; m < M; ++m) pa[m] = make_float4(0.f, 0.f, 0.f, 0.f);
            #pragma unroll
            for (int j = 0; j < 2; ++j) {
                float4 yv[M];
                #pragma unroll
                for (int m = 0; m < M; ++m) yv[m] = C4[m * 8 + ss * 2 + j];
                #pragma unroll
                for (int i2 = 0; i2 < 4; ++i2) {
                    int row = j0 + ss * 8 + j * 4 + i2;
                    float4 w = Wo4[row * 64 + cc];
                    #pragma unroll
                    for (int m = 0; m < M; ++m) FMA_C(pa[m], w, yv[m], i2);
                }
            }
            #pragma unroll
            for (int m = 0; m < M; ++m) ps4[m * 264 + ss * 66 + cc] = pa[m];
            __syncthreads();
            reduce_scatter();
        }
        cluster.sync();
        tiny_stage(bo + l * D);
        cluster.sync();

        // ================== heavy stage B: MLP pair ==================
        ln_normalize(ln2_s + l * D, ln2_b + l * D);
        {
            // (1) g chunk = gelu(y @ w1[:, j0b:j0b+128] + b1)
            const float4* W14 = (const float4*)(w1 + (size_t)l * D * F);
            float4 a[M];
            #pragma unroll
            for (int m = 0; m < M; ++m) a[m] = make_float4(0.f, 0.f, 0.f, 0.f);
            #pragma unroll
            for (int j = 0; j < 8; ++j) {
                float4 yv[M];
                #pragma unroll
                for (int m = 0; m < M; ++m) yv[m] = Y4[m * 64 + ksb * 8 + j];
                #pragma unroll
                for (int i2 = 0; i2 < 4; ++i2) {
                    int k = ksb * 32 + j * 4 + i2;
                    float4 w = W14[k * 256 + r * 32 + c4b];
                    #pragma unroll
                    for (int m = 0; m < M; ++m) FMA_C(a[m], w, yv[m], i2);
                }
            }
            #pragma unroll
            for (int m = 0; m < M; ++m) ps4[ksb * 128 + m * 32 + c4b] = a[m];
            __syncthreads();
            #pragma unroll
            for (int t = 0; t < 2; ++t) {
                int o = tid + t * 256;
                int m = o >> 7, col = o & 127;
                float acc = b1v[l * F + j0b + col];
                #pragma unroll
                for (int s = 0; s < 8; ++s) acc += psf[s * 512 + m * 128 + col];
                sh_c[m * 128 + col] = gelu_tanh(acc);
            }
            __syncthreads();

            // (2) partial delta (all 256 cols) from my g chunk rows of w2
            const float4* W24 = (const float4*)(w2 + (size_t)l * F * D);
            float4 pa[M];
            #pragma unroll
            for (int m = 0; m < M; ++m) pa[m] = make_float4(0.f, 0.f, 0.f, 0.f);
            #pragma unroll
            for (int j = 0; j < 8; ++j) {
                float4 yv[M];
                #pragma unroll
                for (int m = 0; m < M; ++m) yv[m] = C4[m * 32 + ss * 8 + j];
                #pragma unroll
                for (int i2 = 0; i2 < 4; ++i2) {
                    int row = j0b + ss * 32 + j * 4 + i2;
                    float4 w = W24[row * 64 + cc];
                    #pragma unroll
                    for (int m = 0; m < M; ++m) FMA_C(pa[m], w, yv[m], i2);
                }
            }
            #pragma unroll
            for (int m = 0; m < M; ++m) ps4[m * 264 + ss * 66 + cc] = pa[m];
            __syncthreads();
            reduce_scatter();
        }
        cluster.sync();
        tiny_stage(b2v + l * D);
        cluster.sync();
    }

    // ================== classifier (rank 0) ==================
    if (r == 0) {
        if (tid < 160) {
            const int c = tid >> 4;
            const int s = tid & 15;
            #pragma unroll
            for (int m = 0; m < M; ++m) {
                float acc = 0.0f;
                #pragma unroll
                for (int i = 0; i < 16; ++i) {
                    int k = s * 16 + i;
                    acc = fmaf(sh_h[m * D + k], wcls[k * NC + c], acc);
                }
                psf[m * 176 + c * 17 + s] = acc;
            }
        }
        __syncthreads();
        if (tid < NC) {
            #pragma unroll
            for (int m = 0; m < M; ++m) {
                float acc = bcls[tid];
                #pragma unroll
                for (int s = 0; s < 16; ++s) acc += psf[m * 176 + tid * 17 + s];
                out[(size_t)(b0 + m) * NC + tid] = acc;
            }
        }
    }
}

extern "C" void kernel_launch(void* const* d_in, const int* in_sizes, int n_in,
                              void* d_out, int out_size)
{
    const int*   xx      = (const int*)  d_in[0];
    const float* emb_tok = (const float*)d_in[1];
    const float* emb_pos = (const float*)d_in[2];
    const float* ln1_s   = (const float*)d_in[4];
    const float* ln1_b   = (const float*)d_in[5];
    const float* wv      = (const float*)d_in[8];
    const float* wo      = (const float*)d_in[9];
    const float* bo      = (const float*)d_in[10];
    const float* ln2_s   = (const float*)d_in[11];
    const float* ln2_b   = (const float*)d_in[12];
    const float* w1      = (const float*)d_in[13];
    const float* b1v     = (const float*)d_in[14];
    const float* w2      = (const float*)d_in[15];
    const float* b2v     = (const float*)d_in[16];
    const float* wcls    = (const float*)d_in[17];
    const float* bcls    = (const float*)d_in[18];
    float* out = (float*)d_out;

    const int B = out_size / NC;          // 16
    const int N = in_sizes[0] / B;        // 4096
    const int grid = (B / M) * CS;        // 32 blocks = 4 clusters

    performer_cls_kernel<<<grid, TPB>>>(xx, emb_tok, emb_pos, ln1_s, ln1_b,
                                        wv, wo, bo, ln2_s, ln2_b,
                                        w1, b1v, w2, b2v, wcls, bcls, out, N);
}